// round 10
// baseline (speedup 1.0000x reference)
#include <cuda_runtime.h>
#include <cuda_fp16.h>
#include <math.h>
#include <stdint.h>

#define TDIM 512
#define TOUT 1024
#define TBATCH 65536

// Scratch: W converted to fp16 (1MB) + inv_freq table (device globals = legal scratch).
__device__ __half g_W16[TOUT * TDIM];
__device__ float  g_invf[TDIM];

// Elements per 256-row x 512-col W chunk (g_W16 is __half*, arithmetic in ELEMENTS).
#define W_CHUNK_ELEMS 131072

__global__ void prep_kernel(const float* __restrict__ W) {
    int idx = blockIdx.x * blockDim.x + threadIdx.x;
    if (idx < TOUT * TDIM)
        g_W16[idx] = __float2half_rn(W[idx]);
    if (idx < TDIM) {
        float a  = (2.0f * (float)idx) / 512.0f;
        float xf = __fmul_rn(a, 9.210340371976184f);
        g_invf[idx] = (float)exp(-(double)xf);
    }
}

// Accurate sin/cos for x in [0, ~1024] rad. odd=0 -> sin, odd=1 -> cos.
__device__ __forceinline__ float sincos_sel(float x, int odd) {
    float j  = __fmaf_rn(x, 0.63661977236758134f, 12582912.0f);
    int   qi = __float_as_int(j);
    float jf = __fadd_rn(j, -12582912.0f);
    float r  = __fmaf_rn(jf, -1.57079601e+00f, x);
    r        = __fmaf_rn(jf, -3.13916473e-07f, r);
    r        = __fmaf_rn(jf, -5.39030253e-15f, r);
    float r2 = __fmul_rn(r, r);
    float ps = __fmaf_rn(2.75573192e-6f, r2, -1.98412698e-4f);
    ps = __fmaf_rn(ps, r2, 8.33333333e-3f);
    ps = __fmaf_rn(ps, r2, -1.66666667e-1f);
    float sp = __fmaf_rn(ps * r2, r, r);
    float pc = __fmaf_rn(2.48015873e-5f, r2, -1.38888889e-3f);
    pc = __fmaf_rn(pc, r2, 4.16666667e-2f);
    pc = __fmaf_rn(pc, r2, -5.0e-1f);
    float cp = __fmaf_rn(pc, r2, 1.0f);
    int qq = qi + odd;
    float v = (qq & 1) ? cp : sp;
    return (qq & 2) ? -v : v;
}

#define CP_ASYNC16(dst, src) \
    asm volatile("cp.async.cg.shared.global [%0], [%1], 16;" :: "r"(dst), "l"(src))
#define CP_COMMIT()  asm volatile("cp.async.commit_group;")
#define CP_WAIT1()   asm volatile("cp.async.wait_group 1;")
#define CP_WAIT0()   asm volatile("cp.async.wait_group 0;")

// --------------------------- SMEM layout (k-plane, no swizzle) --------------
// A: 64 k-planes of [128 rows x 16B], plane stride 2080 (32B skew) = 133120 B
//    element (row, k): plane u = k>>3, byte = u*2080 + row*16 + (k&7)*2
// B ring: 3 stages; stage = 8 k-planes of [256 n x 16B], plane stride 4096
//    element (n, k within 64-tile): u = k>>3, byte = u*4096 + n*16 + (k&7)*2
#define A_OFF     0
#define A_PLANE   2080
#define B_OFF     133120
#define B_PLANE   4096
#define B_STAGE   32768
#define SMEM_TOTAL 231424

__device__ __forceinline__ void ldmat4(uint32_t addr, uint32_t* r) {
    asm volatile("ldmatrix.sync.aligned.m8n8.x4.shared.b16 {%0,%1,%2,%3}, [%4];"
                 : "=r"(r[0]), "=r"(r[1]), "=r"(r[2]), "=r"(r[3]) : "r"(addr));
}

__global__ void __launch_bounds__(1024, 1) temb_main(
    const float* __restrict__ T,
    const float* __restrict__ bias,
    float* __restrict__ out)
{
    extern __shared__ char smem[];
    const int tid = threadIdx.x;
    const int mbase = blockIdx.x * 128;
    uint32_t sbase;
    asm("{ .reg .u64 t; cvta.to.shared.u64 t, %1; cvt.u32.u64 %0, t; }"
        : "=r"(sbase) : "l"(smem));

    // ---- cp.async per-thread offsets (2 x 16B per thread per stage) ----
    // Chunk id e in [0,2048): plane u = e>>8 (0..7), row n = e&255.
    // Consecutive lanes -> consecutive n within one plane: contiguous 512B per
    // warp -> conflict-free smem stores (n-fastest; u-fastest would alias banks
    // at stride 4096).
    uint32_t cp_dst[2], cp_src[2];
    #pragma unroll
    for (int i = 0; i < 2; i++) {
        int e = i * 1024 + tid;
        int u = e >> 8, n = e & 255;
        cp_dst[i] = (uint32_t)(u * B_PLANE + n * 16);
        cp_src[i] = (uint32_t)(n * 512 + u * 8);  // element offset in W row-block
    }

    // ---- Prologue: start B pipeline for stages 0,1 ----
    #pragma unroll
    for (int s = 0; s < 2; s++) {
        const __half* sb = g_W16 + (size_t)(s >> 3) * W_CHUNK_ELEMS + (s & 7) * 64;
        uint32_t db = sbase + B_OFF + (uint32_t)(s % 3) * B_STAGE;
        #pragma unroll
        for (int i = 0; i < 2; i++)
            CP_ASYNC16(db + cp_dst[i], (const void*)(sb + cp_src[i]));
        CP_COMMIT();
    }

    // ---- Phase 1: embedding -> A smem (k-plane layout), overlaps cp.async ----
    for (int p = tid; p < 128 * 256; p += 1024) {
        int row = p >> 8;
        int c2  = (p & 255) * 2;
        float t  = __ldg(&T[mbase + row]);
        float e0 = sincos_sel(__fmul_rn(t, g_invf[c2]), 0);
        float e1 = sincos_sel(__fmul_rn(t, g_invf[c2 + 1]), 1);
        __half2 h = __floats2half2_rn(e0, e1);
        int u = c2 >> 3;
        *(__half2*)(smem + A_OFF + u * A_PLANE + row * 16 + ((c2 & 7) << 1)) = h;
    }

    // ---- Warp tiling: 32 warps = 4M x 8N, warp tile 32M x 32N ----
    const int lane = tid & 31;
    const int w    = tid >> 5;
    const int mw   = (w & 3) * 32;       // warp M offset (0..96)
    const int nwg  = (w >> 2) * 32;      // warp N offset within 256-chunk (0..224)
    const int arow0 = mw + ((lane >> 3) & 1) * 8 + (lane & 7);
    const int a_c8  = lane >> 4;                        // A k-unit select (0/1)
    const int bn0   = (lane & 7) + ((lane >> 4) << 3);  // B n select (0..15)
    const int b_k8  = (lane >> 3) & 1;                  // B k-unit select (0/1)

    // Per-lane invariant bases (plane-relative); per-kk deltas are constants.
    const uint32_t a_base0 = sbase + A_OFF + (uint32_t)a_c8 * A_PLANE
                           + (uint32_t)arow0 * 16u;             // mt=0
    const uint32_t b_base  = (uint32_t)b_k8 * B_PLANE + (uint32_t)(nwg + bn0) * 16u;

    float acc[2][4][4];   // [mt][n8-tile][quad] = 32 regs

    for (int s = 0; s < 32; s++) {
        const int kt = s & 7, nb = s >> 3, buf = s % 3;

        if (kt == 0) {
            #pragma unroll
            for (int mt = 0; mt < 2; mt++)
                #pragma unroll
                for (int nt = 0; nt < 4; nt++) {
                    acc[mt][nt][0] = 0.f; acc[mt][nt][1] = 0.f;
                    acc[mt][nt][2] = 0.f; acc[mt][nt][3] = 0.f;
                }
        }

        // stage s complete (leave newest group in flight), then publish CTA-wide
        if (s == 31) { CP_WAIT0(); } else { CP_WAIT1(); }
        __syncthreads();

        // issue stage s+2 (buffer (s+2)%3 == (s-1)%3, free after the barrier)
        if (s + 2 < 32) {
            int s2 = s + 2;
            const __half* sb = g_W16 + (size_t)(s2 >> 3) * W_CHUNK_ELEMS + (s2 & 7) * 64;
            uint32_t db = sbase + B_OFF + (uint32_t)(s2 % 3) * B_STAGE;
            #pragma unroll
            for (int i = 0; i < 2; i++)
                CP_ASYNC16(db + cp_dst[i], (const void*)(sb + cp_src[i]));
            CP_COMMIT();
        }

        // ---- MMA over this 64-wide k-tile (pure IADD addressing) ----
        const uint32_t a_kt = a_base0 + (uint32_t)(kt * 8) * A_PLANE;
        const uint32_t b_st = sbase + B_OFF + (uint32_t)buf * B_STAGE + b_base;
        #pragma unroll
        for (int kk = 0; kk < 4; kk++) {
            uint32_t a[2][4];
            const uint32_t a_kk = a_kt + (uint32_t)(kk * 2) * A_PLANE;
            ldmat4(a_kk, a[0]);
            ldmat4(a_kk + 256u, a[1]);          // +16 rows * 16B
            const uint32_t b_kk = b_st + (uint32_t)(kk * 2) * B_PLANE;
            #pragma unroll
            for (int j = 0; j < 2; j++) {
                uint32_t b[4];
                ldmat4(b_kk + (uint32_t)(j * 16) * 16u, b);
                #pragma unroll
                for (int mt = 0; mt < 2; mt++) {
                    asm volatile(
                        "mma.sync.aligned.m16n8k16.row.col.f32.f16.f16.f32 "
                        "{%0,%1,%2,%3}, {%4,%5,%6,%7}, {%8,%9}, {%0,%1,%2,%3};"
                        : "+f"(acc[mt][2*j][0]), "+f"(acc[mt][2*j][1]),
                          "+f"(acc[mt][2*j][2]), "+f"(acc[mt][2*j][3])
                        : "r"(a[mt][0]), "r"(a[mt][1]), "r"(a[mt][2]), "r"(a[mt][3]),
                          "r"(b[0]), "r"(b[1]));
                    asm volatile(
                        "mma.sync.aligned.m16n8k16.row.col.f32.f16.f16.f32 "
                        "{%0,%1,%2,%3}, {%4,%5,%6,%7}, {%8,%9}, {%0,%1,%2,%3};"
                        : "+f"(acc[mt][2*j+1][0]), "+f"(acc[mt][2*j+1][1]),
                          "+f"(acc[mt][2*j+1][2]), "+f"(acc[mt][2*j+1][3])
                        : "r"(a[mt][0]), "r"(a[mt][1]), "r"(a[mt][2]), "r"(a[mt][3]),
                          "r"(b[2]), "r"(b[3]));
                }
            }
        }

        // ---- Epilogue for finished 256-col chunk (overlaps in-flight cp.async) ----
        if (kt == 7) {
            const int nchunk = nb * 256;
            #pragma unroll
            for (int mt = 0; mt < 2; mt++) {
                int row = mbase + mw + mt * 16 + (lane >> 2);
                #pragma unroll
                for (int nt = 0; nt < 4; nt++) {
                    int col = nchunk + nwg + nt * 8 + (lane & 3) * 2;
                    float2 bv = *(const float2*)(bias + col);
                    float v0 = acc[mt][nt][0] + bv.x;
                    float v1 = acc[mt][nt][1] + bv.y;
                    float v2 = acc[mt][nt][2] + bv.x;
                    float v3 = acc[mt][nt][3] + bv.y;
                    v0 = v0 / (1.0f + __expf(-v0));
                    v1 = v1 / (1.0f + __expf(-v1));
                    v2 = v2 / (1.0f + __expf(-v2));
                    v3 = v3 / (1.0f + __expf(-v3));
                    *(float2*)(out + (size_t)row * 1024 + col)       = make_float2(v0, v1);
                    *(float2*)(out + (size_t)(row + 8) * 1024 + col) = make_float2(v2, v3);
                }
            }
        }
    }
}

// ---------------------------------------------------------------------------
extern "C" void kernel_launch(void* const* d_in, const int* in_sizes, int n_in,
                              void* d_out, int out_size) {
    const float* T = (const float*)d_in[0];
    const float* W = (const float*)d_in[1];
    const float* b = (const float*)d_in[2];
    float* out = (float*)d_out;

    prep_kernel<<<(TOUT * TDIM + 255) / 256, 256>>>(W);

    cudaFuncSetAttribute(temb_main, cudaFuncAttributeMaxDynamicSharedMemorySize, SMEM_TOTAL);
    temb_main<<<TBATCH / 128, 1024, SMEM_TOTAL>>>(T, b, out);
}

// round 11
// speedup vs baseline: 1.2960x; 1.2960x over previous
#include <cuda_runtime.h>
#include <cuda_fp16.h>
#include <math.h>
#include <stdint.h>

#define TDIM 512
#define TOUT 1024
#define TBATCH 65536

// Scratch: W in fp16, PRE-TRANSPOSED into staged k-plane order (device globals
// = legal scratch), + inv_freq table.
// Stage s (s = c*8+kt, c = 256-row chunk, kt = 64-wide k-tile): 32KB contiguous,
// layout [u][n][j]: element (n, k=kt*64+u*8+j) at stage_base + (u*256+n)*8 + j.
__device__ __half g_W16[TOUT * TDIM];
__device__ float  g_invf[TDIM];

#define STAGE_ELEMS 16384   // 256 n * 64 k

__global__ void prep_kernel(const float* __restrict__ W) {
    int idx = blockIdx.x * blockDim.x + threadIdx.x;
    if (idx < TOUT * TDIM) {
        int stage = idx >> 14;          // /16384
        int rem   = idx & 16383;
        int u = rem >> 11;              // /2048
        int rem2 = rem & 2047;
        int n = rem2 >> 3;
        int j = rem2 & 7;
        int row = (stage >> 3) * 256 + n;
        int col = (stage & 7) * 64 + u * 8 + j;
        g_W16[idx] = __float2half_rn(W[row * 512 + col]);
    }
    if (idx < TDIM) {
        float a  = (2.0f * (float)idx) / 512.0f;
        float xf = __fmul_rn(a, 9.210340371976184f);
        g_invf[idx] = (float)exp(-(double)xf);
    }
}

// Accurate sin/cos for x in [0, ~1024] rad. odd=0 -> sin, odd=1 -> cos.
__device__ __forceinline__ float sincos_sel(float x, int odd) {
    float j  = __fmaf_rn(x, 0.63661977236758134f, 12582912.0f);
    int   qi = __float_as_int(j);
    float jf = __fadd_rn(j, -12582912.0f);
    float r  = __fmaf_rn(jf, -1.57079601e+00f, x);
    r        = __fmaf_rn(jf, -3.13916473e-07f, r);
    r        = __fmaf_rn(jf, -5.39030253e-15f, r);
    float r2 = __fmul_rn(r, r);
    float ps = __fmaf_rn(2.75573192e-6f, r2, -1.98412698e-4f);
    ps = __fmaf_rn(ps, r2, 8.33333333e-3f);
    ps = __fmaf_rn(ps, r2, -1.66666667e-1f);
    float sp = __fmaf_rn(ps * r2, r, r);
    float pc = __fmaf_rn(2.48015873e-5f, r2, -1.38888889e-3f);
    pc = __fmaf_rn(pc, r2, 4.16666667e-2f);
    pc = __fmaf_rn(pc, r2, -5.0e-1f);
    float cp = __fmaf_rn(pc, r2, 1.0f);
    int qq = qi + odd;
    float v = (qq & 1) ? cp : sp;
    return (qq & 2) ? -v : v;
}

#define CP_ASYNC16(dst, src) \
    asm volatile("cp.async.cg.shared.global [%0], [%1], 16;" :: "r"(dst), "l"(src))
#define CP_COMMIT()  asm volatile("cp.async.commit_group;")
#define CP_WAIT1()   asm volatile("cp.async.wait_group 1;")
#define CP_WAIT0()   asm volatile("cp.async.wait_group 0;")

// --------------------------- SMEM layout (k-plane, no swizzle) --------------
// A: 64 k-planes of [128 rows x 16B], plane stride 2080 (32B skew) = 133120 B
// B ring: 3 stages; stage = 8 k-planes of [256 n x 16B], plane stride 4096.
// Staged gmem layout == smem stage layout, so cp.async offsets are identity:
// both sides coalesced/conflict-free.
#define A_OFF     0
#define A_PLANE   2080
#define B_OFF     133120
#define B_PLANE   4096
#define B_STAGE   32768
#define SMEM_TOTAL 231424

__device__ __forceinline__ void ldmat4(uint32_t addr, uint32_t* r) {
    asm volatile("ldmatrix.sync.aligned.m8n8.x4.shared.b16 {%0,%1,%2,%3}, [%4];"
                 : "=r"(r[0]), "=r"(r[1]), "=r"(r[2]), "=r"(r[3]) : "r"(addr));
}

__global__ void __launch_bounds__(1024, 1) temb_main(
    const float* __restrict__ T,
    const float* __restrict__ bias,
    float* __restrict__ out)
{
    extern __shared__ char smem[];
    const int tid = threadIdx.x;
    const int mbase = blockIdx.x * 128;
    uint32_t sbase;
    asm("{ .reg .u64 t; cvta.to.shared.u64 t, %1; cvt.u32.u64 %0, t; }"
        : "=r"(sbase) : "l"(smem));

    // Identity copy: 2048 16B chunks per stage, 2 per thread. Byte offset
    // e*16 on BOTH sides -> gmem fully coalesced, smem conflict-free.
    const uint32_t cp_off0 = (uint32_t)tid * 16u;
    const uint32_t cp_off1 = cp_off0 + 16384u;

    // ---- Prologue: start B pipeline for stages 0,1 ----
    #pragma unroll
    for (int s = 0; s < 2; s++) {
        const char* sb = (const char*)g_W16 + (size_t)s * (STAGE_ELEMS * 2);
        uint32_t db = sbase + B_OFF + (uint32_t)(s % 3) * B_STAGE;
        CP_ASYNC16(db + cp_off0, sb + cp_off0);
        CP_ASYNC16(db + cp_off1, sb + cp_off1);
        CP_COMMIT();
    }

    // ---- Phase 1: embedding -> A smem (k-plane layout), overlaps cp.async ----
    for (int p = tid; p < 128 * 256; p += 1024) {
        int row = p >> 8;
        int c2  = (p & 255) * 2;
        float t  = __ldg(&T[mbase + row]);
        float e0 = sincos_sel(__fmul_rn(t, g_invf[c2]), 0);
        float e1 = sincos_sel(__fmul_rn(t, g_invf[c2 + 1]), 1);
        __half2 h = __floats2half2_rn(e0, e1);
        int u = c2 >> 3;
        *(__half2*)(smem + A_OFF + u * A_PLANE + row * 16 + ((c2 & 7) << 1)) = h;
    }

    // ---- Warp tiling: 32 warps = 4M x 8N, warp tile 32M x 32N ----
    const int lane = tid & 31;
    const int w    = tid >> 5;
    const int mw   = (w & 3) * 32;       // warp M offset (0..96)
    const int nwg  = (w >> 2) * 32;      // warp N offset within 256-chunk (0..224)
    const int arow0 = mw + ((lane >> 3) & 1) * 8 + (lane & 7);
    const int a_c8  = lane >> 4;                        // A k-unit select (0/1)
    const int bn0   = (lane & 7) + ((lane >> 4) << 3);  // B n select (0..15)
    const int b_k8  = (lane >> 3) & 1;                  // B k-unit select (0/1)

    const uint32_t a_base0 = sbase + A_OFF + (uint32_t)a_c8 * A_PLANE
                           + (uint32_t)arow0 * 16u;
    const uint32_t b_base  = (uint32_t)b_k8 * B_PLANE + (uint32_t)(nwg + bn0) * 16u;

    float acc[2][4][4];   // [mt][n8-tile][quad] = 32 regs

    for (int s = 0; s < 32; s++) {
        const int kt = s & 7, nb = s >> 3, buf = s % 3;

        if (kt == 0) {
            #pragma unroll
            for (int mt = 0; mt < 2; mt++)
                #pragma unroll
                for (int nt = 0; nt < 4; nt++) {
                    acc[mt][nt][0] = 0.f; acc[mt][nt][1] = 0.f;
                    acc[mt][nt][2] = 0.f; acc[mt][nt][3] = 0.f;
                }
        }

        // stage s complete (leave newest group in flight), then publish CTA-wide
        if (s == 31) { CP_WAIT0(); } else { CP_WAIT1(); }
        __syncthreads();

        // issue stage s+2 (buffer (s+2)%3 == (s-1)%3, free after the barrier)
        if (s + 2 < 32) {
            int s2 = s + 2;
            const char* sb = (const char*)g_W16 + (size_t)s2 * (STAGE_ELEMS * 2);
            uint32_t db = sbase + B_OFF + (uint32_t)(s2 % 3) * B_STAGE;
            CP_ASYNC16(db + cp_off0, sb + cp_off0);
            CP_ASYNC16(db + cp_off1, sb + cp_off1);
            CP_COMMIT();
        }

        // ---- MMA over this 64-wide k-tile (pure IADD addressing) ----
        const uint32_t a_kt = a_base0 + (uint32_t)(kt * 8) * A_PLANE;
        const uint32_t b_st = sbase + B_OFF + (uint32_t)buf * B_STAGE + b_base;
        #pragma unroll
        for (int kk = 0; kk < 4; kk++) {
            uint32_t a[2][4];
            const uint32_t a_kk = a_kt + (uint32_t)(kk * 2) * A_PLANE;
            ldmat4(a_kk, a[0]);
            ldmat4(a_kk + 256u, a[1]);          // +16 rows * 16B
            const uint32_t b_kk = b_st + (uint32_t)(kk * 2) * B_PLANE;
            #pragma unroll
            for (int j = 0; j < 2; j++) {
                uint32_t b[4];
                ldmat4(b_kk + (uint32_t)(j * 16) * 16u, b);
                #pragma unroll
                for (int mt = 0; mt < 2; mt++) {
                    asm volatile(
                        "mma.sync.aligned.m16n8k16.row.col.f32.f16.f16.f32 "
                        "{%0,%1,%2,%3}, {%4,%5,%6,%7}, {%8,%9}, {%0,%1,%2,%3};"
                        : "+f"(acc[mt][2*j][0]), "+f"(acc[mt][2*j][1]),
                          "+f"(acc[mt][2*j][2]), "+f"(acc[mt][2*j][3])
                        : "r"(a[mt][0]), "r"(a[mt][1]), "r"(a[mt][2]), "r"(a[mt][3]),
                          "r"(b[0]), "r"(b[1]));
                    asm volatile(
                        "mma.sync.aligned.m16n8k16.row.col.f32.f16.f16.f32 "
                        "{%0,%1,%2,%3}, {%4,%5,%6,%7}, {%8,%9}, {%0,%1,%2,%3};"
                        : "+f"(acc[mt][2*j+1][0]), "+f"(acc[mt][2*j+1][1]),
                          "+f"(acc[mt][2*j+1][2]), "+f"(acc[mt][2*j+1][3])
                        : "r"(a[mt][0]), "r"(a[mt][1]), "r"(a[mt][2]), "r"(a[mt][3]),
                          "r"(b[2]), "r"(b[3]));
                }
            }
        }

        // ---- Epilogue for finished 256-col chunk (overlaps in-flight cp.async) ----
        if (kt == 7) {
            const int nchunk = nb * 256;
            #pragma unroll
            for (int mt = 0; mt < 2; mt++) {
                int row = mbase + mw + mt * 16 + (lane >> 2);
                #pragma unroll
                for (int nt = 0; nt < 4; nt++) {
                    int col = nchunk + nwg + nt * 8 + (lane & 3) * 2;
                    float2 bv = *(const float2*)(bias + col);
                    float v0 = acc[mt][nt][0] + bv.x;
                    float v1 = acc[mt][nt][1] + bv.y;
                    float v2 = acc[mt][nt][2] + bv.x;
                    float v3 = acc[mt][nt][3] + bv.y;
                    v0 = v0 / (1.0f + __expf(-v0));
                    v1 = v1 / (1.0f + __expf(-v1));
                    v2 = v2 / (1.0f + __expf(-v2));
                    v3 = v3 / (1.0f + __expf(-v3));
                    *(float2*)(out + (size_t)row * 1024 + col)       = make_float2(v0, v1);
                    *(float2*)(out + (size_t)(row + 8) * 1024 + col) = make_float2(v2, v3);
                }
            }
        }
    }
}

// ---------------------------------------------------------------------------
extern "C" void kernel_launch(void* const* d_in, const int* in_sizes, int n_in,
                              void* d_out, int out_size) {
    const float* T = (const float*)d_in[0];
    const float* W = (const float*)d_in[1];
    const float* b = (const float*)d_in[2];
    float* out = (float*)d_out;

    prep_kernel<<<(TOUT * TDIM + 255) / 256, 256>>>(W);

    cudaFuncSetAttribute(temb_main, cudaFuncAttributeMaxDynamicSharedMemorySize, SMEM_TOTAL);
    temb_main<<<TBATCH / 128, 1024, SMEM_TOTAL>>>(T, b, out);
}

// round 12
// speedup vs baseline: 1.3669x; 1.0547x over previous
#include <cuda_runtime.h>
#include <cuda_fp16.h>
#include <math.h>
#include <stdint.h>

#define TDIM 512
#define TOUT 1024
#define TBATCH 65536

// W in fp16, pre-transposed into per-(stage, group) 4KB blocks:
// block id b = (s*8 + g), s = c*8+kt (c: 256-row chunk, kt: 64-wide k-tile),
// g: 32-row group slice. Within block: elem (n',k=u*8+j) at (u*32+n')*8+j.
__device__ __half g_W16[TOUT * TDIM];
__device__ float  g_invf[TDIM];

__global__ void prep_kernel(const float* __restrict__ W) {
    int idx = blockIdx.x * blockDim.x + threadIdx.x;
    if (idx < TOUT * TDIM) {
        int b      = idx >> 11;            // 4KB block = 2048 elems
        int within = idx & 2047;
        int u  = within >> 8;              // k-unit 0..7
        int np = (within >> 3) & 31;       // local row 0..31
        int j  = within & 7;
        int g  = b & 7;
        int kt = (b >> 3) & 7;
        int c  = b >> 6;
        int row = c * 256 + g * 32 + np;
        int col = kt * 64 + u * 8 + j;
        g_W16[idx] = __float2half_rn(W[row * 512 + col]);
    }
    if (idx < TDIM) {
        float a  = (2.0f * (float)idx) / 512.0f;
        float xf = __fmul_rn(a, 9.210340371976184f);
        g_invf[idx] = (float)exp(-(double)xf);
    }
}

// Accurate sin/cos for x in [0, ~1024] rad. odd=0 -> sin, odd=1 -> cos.
__device__ __forceinline__ float sincos_sel(float x, int odd) {
    float j  = __fmaf_rn(x, 0.63661977236758134f, 12582912.0f);
    int   qi = __float_as_int(j);
    float jf = __fadd_rn(j, -12582912.0f);
    float r  = __fmaf_rn(jf, -1.57079601e+00f, x);
    r        = __fmaf_rn(jf, -3.13916473e-07f, r);
    r        = __fmaf_rn(jf, -5.39030253e-15f, r);
    float r2 = __fmul_rn(r, r);
    float ps = __fmaf_rn(2.75573192e-6f, r2, -1.98412698e-4f);
    ps = __fmaf_rn(ps, r2, 8.33333333e-3f);
    ps = __fmaf_rn(ps, r2, -1.66666667e-1f);
    float sp = __fmaf_rn(ps * r2, r, r);
    float pc = __fmaf_rn(2.48015873e-5f, r2, -1.38888889e-3f);
    pc = __fmaf_rn(pc, r2, 4.16666667e-2f);
    pc = __fmaf_rn(pc, r2, -5.0e-1f);
    float cp = __fmaf_rn(pc, r2, 1.0f);
    int qq = qi + odd;
    float v = (qq & 1) ? cp : sp;
    return (qq & 2) ? -v : v;
}

#define CP_ASYNC16(dst, src) \
    asm volatile("cp.async.cg.shared.global [%0], [%1], 16;" :: "r"(dst), "l"(src))
#define CP_COMMIT()  asm volatile("cp.async.commit_group;")
#define CP_WAIT1()   asm volatile("cp.async.wait_group 1;")
#define CP_WAIT0()   asm volatile("cp.async.wait_group 0;")
#define GBAR(id)     asm volatile("bar.sync %0, 128;" :: "r"(id) : "memory")

// --------------------------- SMEM layout ------------------------------------
// A: 64 k-planes of [128 rows x 16B], plane stride 2080 (32B skew) = 133120 B
// B: 8 group-private rings, 3 stages x 4KB each (32 n x 64 k fp16) = 98304 B
#define A_OFF     0
#define A_PLANE   2080
#define B_OFF     133120
#define B_SLICE   4096
#define SMEM_TOTAL 231424

__device__ __forceinline__ void ldmat4(uint32_t addr, uint32_t* r) {
    asm volatile("ldmatrix.sync.aligned.m8n8.x4.shared.b16 {%0,%1,%2,%3}, [%4];"
                 : "=r"(r[0]), "=r"(r[1]), "=r"(r[2]), "=r"(r[3]) : "r"(addr));
}

__global__ void __launch_bounds__(1024, 1) temb_main(
    const float* __restrict__ T,
    const float* __restrict__ bias,
    float* __restrict__ out)
{
    extern __shared__ char smem[];
    const int tid = threadIdx.x;
    const int mbase = blockIdx.x * 128;
    uint32_t sbase;
    asm("{ .reg .u64 t; cvta.to.shared.u64 t, %1; cvt.u32.u64 %0, t; }"
        : "=r"(sbase) : "l"(smem));

    const int w      = tid >> 5;
    const int lane   = tid & 31;
    const int g      = w >> 2;          // B-slice group (0..7), 128 threads each
    const int mw     = (w & 3) * 32;    // warp M offset within CTA tile
    const int wg_tid = tid & 127;

    // Group-private ring base and cp.async offsets (identity copy: 4KB slice,
    // 2 x 16B per thread, contiguous on both sides).
    const uint32_t ring   = sbase + B_OFF + (uint32_t)(g * 3) * B_SLICE;
    const uint32_t cp0    = (uint32_t)wg_tid * 16u;
    const uint32_t cp1    = cp0 + 2048u;
    const char*    wsrc   = (const char*)g_W16;   // byte base; block (s*8+g)*4096

    // ---- Prologue: start this group's pipeline for stages 0,1 ----
    #pragma unroll
    for (int s = 0; s < 2; s++) {
        const char* sb = wsrc + (size_t)(s * 8 + g) * 4096;
        uint32_t db = ring + (uint32_t)(s % 3) * B_SLICE;
        CP_ASYNC16(db + cp0, sb + cp0);
        CP_ASYNC16(db + cp1, sb + cp1);
        CP_COMMIT();
    }

    // ---- Phase 1: embedding -> A smem (k-plane layout), overlaps cp.async ----
    for (int p = tid; p < 128 * 256; p += 1024) {
        int row = p >> 8;
        int c2  = (p & 255) * 2;
        float t  = __ldg(&T[mbase + row]);
        float e0 = sincos_sel(__fmul_rn(t, g_invf[c2]), 0);
        float e1 = sincos_sel(__fmul_rn(t, g_invf[c2 + 1]), 1);
        __half2 h = __floats2half2_rn(e0, e1);
        int u = c2 >> 3;
        *(__half2*)(smem + A_OFF + u * A_PLANE + row * 16 + ((c2 & 7) << 1)) = h;
    }
    __syncthreads();    // A ready; ONLY CTA-wide barrier. Groups free-run after.

    // ---- ldmatrix lane geometry ----
    const int arow0 = mw + ((lane >> 3) & 1) * 8 + (lane & 7);
    const int a_c8  = lane >> 4;
    const int bn0   = (lane & 7) + ((lane >> 4) << 3);  // local n 0..15
    const int b_k8  = (lane >> 3) & 1;

    const uint32_t a_base0 = sbase + A_OFF + (uint32_t)a_c8 * A_PLANE
                           + (uint32_t)arow0 * 16u;
    const uint32_t b_lane  = (uint32_t)b_k8 * 512u + (uint32_t)bn0 * 16u;

    float acc[2][4][4];   // [mt][n8-tile][quad] = 32 regs

    for (int s = 0; s < 32; s++) {
        const int kt = s & 7, nb = s >> 3, buf = s % 3;

        if (kt == 0) {
            #pragma unroll
            for (int mt = 0; mt < 2; mt++)
                #pragma unroll
                for (int nt = 0; nt < 4; nt++) {
                    acc[mt][nt][0] = 0.f; acc[mt][nt][1] = 0.f;
                    acc[mt][nt][2] = 0.f; acc[mt][nt][3] = 0.f;
                }
        }

        // Group-local: own cp.asyncs done (leave newest in flight), then
        // publish slice within the 128-thread group only.
        if (s == 31) { CP_WAIT0(); } else { CP_WAIT1(); }
        GBAR(g + 1);

        // issue stage s+2 into buffer (s+2)%3 (free: last read at iter s-1,
        // republished only after this group's barrier above)
        if (s + 2 < 32) {
            int s2 = s + 2;
            const char* sb = wsrc + (size_t)(s2 * 8 + g) * 4096;
            uint32_t db = ring + (uint32_t)(s2 % 3) * B_SLICE;
            CP_ASYNC16(db + cp0, sb + cp0);
            CP_ASYNC16(db + cp1, sb + cp1);
            CP_COMMIT();
        }

        // ---- MMA over this 64-wide k-tile ----
        const uint32_t a_kt = a_base0 + (uint32_t)(kt * 8) * A_PLANE;
        const uint32_t b_st = ring + (uint32_t)buf * B_SLICE + b_lane;
        #pragma unroll
        for (int kk = 0; kk < 4; kk++) {
            uint32_t a[2][4];
            const uint32_t a_kk = a_kt + (uint32_t)(kk * 2) * A_PLANE;
            ldmat4(a_kk, a[0]);
            ldmat4(a_kk + 256u, a[1]);          // +16 rows * 16B
            const uint32_t b_kk = b_st + (uint32_t)kk * 1024u;  // kk*2 planes * 512B
            #pragma unroll
            for (int j = 0; j < 2; j++) {
                uint32_t b[4];
                ldmat4(b_kk + (uint32_t)j * 256u, b);           // +16 local rows
                #pragma unroll
                for (int mt = 0; mt < 2; mt++) {
                    asm volatile(
                        "mma.sync.aligned.m16n8k16.row.col.f32.f16.f16.f32 "
                        "{%0,%1,%2,%3}, {%4,%5,%6,%7}, {%8,%9}, {%0,%1,%2,%3};"
                        : "+f"(acc[mt][2*j][0]), "+f"(acc[mt][2*j][1]),
                          "+f"(acc[mt][2*j][2]), "+f"(acc[mt][2*j][3])
                        : "r"(a[mt][0]), "r"(a[mt][1]), "r"(a[mt][2]), "r"(a[mt][3]),
                          "r"(b[0]), "r"(b[1]));
                    asm volatile(
                        "mma.sync.aligned.m16n8k16.row.col.f32.f16.f16.f32 "
                        "{%0,%1,%2,%3}, {%4,%5,%6,%7}, {%8,%9}, {%0,%1,%2,%3};"
                        : "+f"(acc[mt][2*j+1][0]), "+f"(acc[mt][2*j+1][1]),
                          "+f"(acc[mt][2*j+1][2]), "+f"(acc[mt][2*j+1][3])
                        : "r"(a[mt][0]), "r"(a[mt][1]), "r"(a[mt][2]), "r"(a[mt][3]),
                          "r"(b[2]), "r"(b[3]));
                }
            }
        }

        // ---- Epilogue for finished 256-col chunk ----
        if (kt == 7) {
            const int nchunk = nb * 256 + g * 32;
            #pragma unroll
            for (int mt = 0; mt < 2; mt++) {
                int row = mbase + mw + mt * 16 + (lane >> 2);
                #pragma unroll
                for (int nt = 0; nt < 4; nt++) {
                    int col = nchunk + nt * 8 + (lane & 3) * 2;
                    float2 bv = *(const float2*)(bias + col);
                    float v0 = acc[mt][nt][0] + bv.x;
                    float v1 = acc[mt][nt][1] + bv.y;
                    float v2 = acc[mt][nt][2] + bv.x;
                    float v3 = acc[mt][nt][3] + bv.y;
                    v0 = v0 / (1.0f + __expf(-v0));
                    v1 = v1 / (1.0f + __expf(-v1));
                    v2 = v2 / (1.0f + __expf(-v2));
                    v3 = v3 / (1.0f + __expf(-v3));
                    *(float2*)(out + (size_t)row * 1024 + col)       = make_float2(v0, v1);
                    *(float2*)(out + (size_t)(row + 8) * 1024 + col) = make_float2(v2, v3);
                }
            }
        }
    }
}

// ---------------------------------------------------------------------------
extern "C" void kernel_launch(void* const* d_in, const int* in_sizes, int n_in,
                              void* d_out, int out_size) {
    const float* T = (const float*)d_in[0];
    const float* W = (const float*)d_in[1];
    const float* b = (const float*)d_in[2];
    float* out = (float*)d_out;

    prep_kernel<<<(TOUT * TDIM + 255) / 256, 256>>>(W);

    cudaFuncSetAttribute(temb_main, cudaFuncAttributeMaxDynamicSharedMemorySize, SMEM_TOTAL);
    temb_main<<<TBATCH / 128, 1024, SMEM_TOTAL>>>(T, b, out);
}

// round 13
// speedup vs baseline: 1.4466x; 1.0584x over previous
#include <cuda_runtime.h>
#include <cuda_fp16.h>
#include <math.h>
#include <stdint.h>

#define TDIM 512
#define TOUT 1024
#define TBATCH 65536

// W in fp16, pre-transposed into per-(stage, group) 4KB blocks:
// block id b = (s*8 + g), s = c*8+kt (c: 256-row chunk, kt: 64-wide k-tile),
// g: 32-row N slice. Within block: elem (n',k=u*8+j) at (u*32+n')*8+j.
__device__ __half g_W16[TOUT * TDIM];
__device__ float  g_invf[TDIM];

__global__ void prep_kernel(const float* __restrict__ W) {
    int idx = blockIdx.x * blockDim.x + threadIdx.x;
    if (idx < TOUT * TDIM) {
        int b      = idx >> 11;            // 4KB block = 2048 elems
        int within = idx & 2047;
        int u  = within >> 8;              // k-unit 0..7
        int np = (within >> 3) & 31;       // local row 0..31
        int j  = within & 7;
        int g  = b & 7;
        int kt = (b >> 3) & 7;
        int c  = b >> 6;
        int row = c * 256 + g * 32 + np;
        int col = kt * 64 + u * 8 + j;
        g_W16[idx] = __float2half_rn(W[row * 512 + col]);
    }
    if (idx < TDIM) {
        float a  = (2.0f * (float)idx) / 512.0f;
        float xf = __fmul_rn(a, 9.210340371976184f);
        g_invf[idx] = (float)exp(-(double)xf);
    }
}

// Accurate sin/cos for x in [0, ~1024] rad. odd=0 -> sin, odd=1 -> cos.
__device__ __forceinline__ float sincos_sel(float x, int odd) {
    float j  = __fmaf_rn(x, 0.63661977236758134f, 12582912.0f);
    int   qi = __float_as_int(j);
    float jf = __fadd_rn(j, -12582912.0f);
    float r  = __fmaf_rn(jf, -1.57079601e+00f, x);
    r        = __fmaf_rn(jf, -3.13916473e-07f, r);
    r        = __fmaf_rn(jf, -5.39030253e-15f, r);
    float r2 = __fmul_rn(r, r);
    float ps = __fmaf_rn(2.75573192e-6f, r2, -1.98412698e-4f);
    ps = __fmaf_rn(ps, r2, 8.33333333e-3f);
    ps = __fmaf_rn(ps, r2, -1.66666667e-1f);
    float sp = __fmaf_rn(ps * r2, r, r);
    float pc = __fmaf_rn(2.48015873e-5f, r2, -1.38888889e-3f);
    pc = __fmaf_rn(pc, r2, 4.16666667e-2f);
    pc = __fmaf_rn(pc, r2, -5.0e-1f);
    float cp = __fmaf_rn(pc, r2, 1.0f);
    int qq = qi + odd;
    float v = (qq & 1) ? cp : sp;
    return (qq & 2) ? -v : v;
}

#define CP_ASYNC16(dst, src) \
    asm volatile("cp.async.cg.shared.global [%0], [%1], 16;" :: "r"(dst), "l"(src))
#define CP_COMMIT()  asm volatile("cp.async.commit_group;")
#define CP_WAIT1()   asm volatile("cp.async.wait_group 1;")
#define CP_WAIT0()   asm volatile("cp.async.wait_group 0;")
#define GBAR64(id)   asm volatile("bar.sync %0, 64;" :: "r"(id) : "memory")

// --------------------------- SMEM layout ------------------------------------
// A: 64 k-planes of [128 rows x 16B], plane stride 2080 (32B skew) = 133120 B
// B: 8 group-private rings, 3 stages x 4KB each (32 n x 64 k fp16) = 98304 B
#define A_OFF     0
#define A_PLANE   2080
#define B_OFF     133120
#define B_SLICE   4096
#define SMEM_TOTAL 231424

__device__ __forceinline__ void ldmat4(uint32_t addr, uint32_t* r) {
    asm volatile("ldmatrix.sync.aligned.m8n8.x4.shared.b16 {%0,%1,%2,%3}, [%4];"
                 : "=r"(r[0]), "=r"(r[1]), "=r"(r[2]), "=r"(r[3]) : "r"(addr));
}

// 512 threads, 16 warps = 2M x 8N; warp tile 64M x 32N; acc = 64 regs.
__global__ void __launch_bounds__(512, 1) temb_main(
    const float* __restrict__ T,
    const float* __restrict__ bias,
    float* __restrict__ out)
{
    extern __shared__ char smem[];
    const int tid = threadIdx.x;
    const int mbase = blockIdx.x * 128;
    uint32_t sbase;
    asm("{ .reg .u64 t; cvta.to.shared.u64 t, %1; cvt.u32.u64 %0, t; }"
        : "=r"(sbase) : "l"(smem));

    const int w      = tid >> 5;
    const int lane   = tid & 31;
    const int g      = w >> 1;          // N-slice group (0..7), 2 warps / 64 thr
    const int mw     = (w & 1) * 64;    // warp M offset (0 or 64)
    const int wg_tid = tid & 63;

    // Group-private ring; identity cp.async: 4KB slice, 4 x 16B per thread.
    const uint32_t ring = sbase + B_OFF + (uint32_t)(g * 3) * B_SLICE;
    uint32_t cp_off[4];
    #pragma unroll
    for (int i = 0; i < 4; i++) cp_off[i] = (uint32_t)(wg_tid * 16 + i * 1024);
    const char* wsrc = (const char*)g_W16;

    // ---- Prologue: start this group's pipeline for stages 0,1 ----
    #pragma unroll
    for (int s = 0; s < 2; s++) {
        const char* sb = wsrc + (size_t)(s * 8 + g) * 4096;
        uint32_t db = ring + (uint32_t)(s % 3) * B_SLICE;
        #pragma unroll
        for (int i = 0; i < 4; i++)
            CP_ASYNC16(db + cp_off[i], sb + cp_off[i]);
        CP_COMMIT();
    }

    // ---- Phase 1: embedding -> A smem (k-plane layout), overlaps cp.async ----
    for (int p = tid; p < 128 * 256; p += 512) {
        int row = p >> 8;
        int c2  = (p & 255) * 2;
        float t  = __ldg(&T[mbase + row]);
        float e0 = sincos_sel(__fmul_rn(t, g_invf[c2]), 0);
        float e1 = sincos_sel(__fmul_rn(t, g_invf[c2 + 1]), 1);
        __half2 h = __floats2half2_rn(e0, e1);
        int u = c2 >> 3;
        *(__half2*)(smem + A_OFF + u * A_PLANE + row * 16 + ((c2 & 7) << 1)) = h;
    }
    __syncthreads();    // A ready; ONLY CTA-wide barrier. Groups free-run after.

    // ---- ldmatrix lane geometry ----
    const int arow0 = mw + ((lane >> 3) & 1) * 8 + (lane & 7);
    const int a_c8  = lane >> 4;
    const int bn0   = (lane & 7) + ((lane >> 4) << 3);  // local n 0..15
    const int b_k8  = (lane >> 3) & 1;

    const uint32_t a_base0 = sbase + A_OFF + (uint32_t)a_c8 * A_PLANE
                           + (uint32_t)arow0 * 16u;
    const uint32_t b_lane  = (uint32_t)b_k8 * 512u + (uint32_t)bn0 * 16u;

    float acc[4][4][4];   // [m16-tile][n8-tile][quad] = 64 regs

    for (int s = 0; s < 32; s++) {
        const int kt = s & 7, nb = s >> 3, buf = s % 3;

        if (kt == 0) {
            #pragma unroll
            for (int mt = 0; mt < 4; mt++)
                #pragma unroll
                for (int nt = 0; nt < 4; nt++) {
                    acc[mt][nt][0] = 0.f; acc[mt][nt][1] = 0.f;
                    acc[mt][nt][2] = 0.f; acc[mt][nt][3] = 0.f;
                }
        }

        // Group-local: own cp.asyncs done (leave newest in flight), publish
        // slice within the 64-thread group only.
        if (s == 31) { CP_WAIT0(); } else { CP_WAIT1(); }
        GBAR64(g + 1);

        // issue stage s+2 into buffer (s+2)%3 (free: last read at iter s-1)
        if (s + 2 < 32) {
            int s2 = s + 2;
            const char* sb = wsrc + (size_t)(s2 * 8 + g) * 4096;
            uint32_t db = ring + (uint32_t)(s2 % 3) * B_SLICE;
            #pragma unroll
            for (int i = 0; i < 4; i++)
                CP_ASYNC16(db + cp_off[i], sb + cp_off[i]);
            CP_COMMIT();
        }

        // ---- MMA over this 64-wide k-tile ----
        const uint32_t a_kt = a_base0 + (uint32_t)(kt * 8) * A_PLANE;
        const uint32_t b_st = ring + (uint32_t)buf * B_SLICE + b_lane;
        #pragma unroll
        for (int kk = 0; kk < 4; kk++) {
            uint32_t a[4][4];
            const uint32_t a_kk = a_kt + (uint32_t)(kk * 2) * A_PLANE;
            #pragma unroll
            for (int mt = 0; mt < 4; mt++)
                ldmat4(a_kk + (uint32_t)mt * 256u, a[mt]);   // +16 rows * 16B
            const uint32_t b_kk = b_st + (uint32_t)kk * 1024u;
            #pragma unroll
            for (int j = 0; j < 2; j++) {
                uint32_t b[4];
                ldmat4(b_kk + (uint32_t)j * 256u, b);        // +16 local n rows
                #pragma unroll
                for (int mt = 0; mt < 4; mt++) {
                    asm volatile(
                        "mma.sync.aligned.m16n8k16.row.col.f32.f16.f16.f32 "
                        "{%0,%1,%2,%3}, {%4,%5,%6,%7}, {%8,%9}, {%0,%1,%2,%3};"
                        : "+f"(acc[mt][2*j][0]), "+f"(acc[mt][2*j][1]),
                          "+f"(acc[mt][2*j][2]), "+f"(acc[mt][2*j][3])
                        : "r"(a[mt][0]), "r"(a[mt][1]), "r"(a[mt][2]), "r"(a[mt][3]),
                          "r"(b[0]), "r"(b[1]));
                    asm volatile(
                        "mma.sync.aligned.m16n8k16.row.col.f32.f16.f16.f32 "
                        "{%0,%1,%2,%3}, {%4,%5,%6,%7}, {%8,%9}, {%0,%1,%2,%3};"
                        : "+f"(acc[mt][2*j+1][0]), "+f"(acc[mt][2*j+1][1]),
                          "+f"(acc[mt][2*j+1][2]), "+f"(acc[mt][2*j+1][3])
                        : "r"(a[mt][0]), "r"(a[mt][1]), "r"(a[mt][2]), "r"(a[mt][3]),
                          "r"(b[2]), "r"(b[3]));
                }
            }
        }

        // ---- Epilogue for finished 256-col chunk ----
        if (kt == 7) {
            const int nchunk = nb * 256 + g * 32;
            #pragma unroll
            for (int mt = 0; mt < 4; mt++) {
                int row = mbase + mw + mt * 16 + (lane >> 2);
                #pragma unroll
                for (int nt = 0; nt < 4; nt++) {
                    int col = nchunk + nt * 8 + (lane & 3) * 2;
                    float2 bv = *(const float2*)(bias + col);
                    float v0 = acc[mt][nt][0] + bv.x;
                    float v1 = acc[mt][nt][1] + bv.y;
                    float v2 = acc[mt][nt][2] + bv.x;
                    float v3 = acc[mt][nt][3] + bv.y;
                    v0 = v0 / (1.0f + __expf(-v0));
                    v1 = v1 / (1.0f + __expf(-v1));
                    v2 = v2 / (1.0f + __expf(-v2));
                    v3 = v3 / (1.0f + __expf(-v3));
                    *(float2*)(out + (size_t)row * 1024 + col)       = make_float2(v0, v1);
                    *(float2*)(out + (size_t)(row + 8) * 1024 + col) = make_float2(v2, v3);
                }
            }
        }
    }
}

// ---------------------------------------------------------------------------
extern "C" void kernel_launch(void* const* d_in, const int* in_sizes, int n_in,
                              void* d_out, int out_size) {
    const float* T = (const float*)d_in[0];
    const float* W = (const float*)d_in[1];
    const float* b = (const float*)d_in[2];
    float* out = (float*)d_out;

    prep_kernel<<<(TOUT * TDIM + 255) / 256, 256>>>(W);

    cudaFuncSetAttribute(temb_main, cudaFuncAttributeMaxDynamicSharedMemorySize, SMEM_TOTAL);
    temb_main<<<TBATCH / 128, 512, SMEM_TOTAL>>>(T, b, out);
}